// round 2
// baseline (speedup 1.0000x reference)
#include <cuda_runtime.h>
#include <math.h>

#define VOCAB 32000
#define NTOK  4096

// Scratch: per-row sums (allocation-free per harness rules)
__device__ float g_row_sums[NTOK];

// ---------------------------------------------------------------------------
// Kernel 1: one block per row, sum 32000 fp32 values via float4 loads.
// ---------------------------------------------------------------------------
__global__ void __launch_bounds__(256) row_sum_kernel(const float* __restrict__ x) {
    const int row = blockIdx.x;
    const float4* __restrict__ p =
        reinterpret_cast<const float4*>(x + (size_t)row * VOCAB);
    const int nvec = VOCAB / 4;  // 8000

    float s = 0.0f;
    #pragma unroll 4
    for (int i = threadIdx.x; i < nvec; i += 256) {
        float4 v = p[i];
        s += (v.x + v.y) + (v.z + v.w);
    }

    // warp reduce
    #pragma unroll
    for (int o = 16; o > 0; o >>= 1)
        s += __shfl_xor_sync(0xFFFFFFFFu, s, o);

    __shared__ float wsum[8];
    const int warp = threadIdx.x >> 5;
    if ((threadIdx.x & 31) == 0) wsum[warp] = s;
    __syncthreads();

    if (threadIdx.x < 8) {
        s = wsum[threadIdx.x];
        #pragma unroll
        for (int o = 4; o > 0; o >>= 1)
            s += __shfl_xor_sync(0xFFu, s, o);
        if (threadIdx.x == 0) g_row_sums[row] = s;
    }
}

// ---------------------------------------------------------------------------
// Kernel 2: combine 4096 rows in double precision, write scalar fp32.
//   row_loss(t != 0) = K1 - base*(S - x[row][0] - x[row][t]) - conf*x[row][t]
// Handles target dtype being int32 OR int64 via a deterministic probe:
// viewing the buffer as int32, the odd-indexed words of the first 4096 int32s
// are all zero iff the buffer is int64 (high words of values < 32000).
// ---------------------------------------------------------------------------
__global__ void __launch_bounds__(256) finalize_kernel(
    const float* __restrict__ x,
    const void* __restrict__ target_raw,
    float* __restrict__ out)
{
    const double base = 0.1 / 31999.0;          // SMOOTHING / (V-1)
    const double conf = 0.9;                    // 1 - SMOOTHING
    const double K1 = (double)(VOCAB - 2) * base * log(base) + conf * log(conf);

    const int* __restrict__ t32 = (const int*)target_raw;
    const long long* __restrict__ t64 = (const long long*)target_raw;

    // ---- dtype probe: OR all odd-indexed int32 words in [0, 4096) ----
    __shared__ int s_odd_or;
    if (threadIdx.x == 0) s_odd_or = 0;
    __syncthreads();
    int local_or = 0;
    for (int i = threadIdx.x; i < NTOK / 2; i += 256)
        local_or |= t32[2 * i + 1];
    #pragma unroll
    for (int o = 16; o > 0; o >>= 1)
        local_or |= __shfl_xor_sync(0xFFFFFFFFu, local_or, o);
    if ((threadIdx.x & 31) == 0) atomicOr(&s_odd_or, local_or);
    __syncthreads();
    const bool is64 = (s_odd_or == 0);   // all-zero high words => int64

    // ---- main accumulation ----
    double acc = 0.0;
    for (int r = threadIdx.x; r < NTOK; r += 256) {
        const long long t = is64 ? t64[r] : (long long)t32[r];
        if (t > 0 && t < VOCAB) {
            const double S  = (double)g_row_sums[r];
            const size_t rowoff = (size_t)r * VOCAB;
            const double x0 = (double)x[rowoff];
            const double xt = (double)x[rowoff + (size_t)t];
            acc += K1 - base * (S - x0 - xt) - conf * xt;
        }
    }

    // warp reduce (double)
    #pragma unroll
    for (int o = 16; o > 0; o >>= 1)
        acc += __shfl_xor_sync(0xFFFFFFFFu, acc, o);

    __shared__ double wsum[8];
    const int warp = threadIdx.x >> 5;
    if ((threadIdx.x & 31) == 0) wsum[warp] = acc;
    __syncthreads();

    if (threadIdx.x < 8) {
        acc = wsum[threadIdx.x];
        #pragma unroll
        for (int o = 4; o > 0; o >>= 1)
            acc += __shfl_xor_sync(0xFFu, acc, o);
        if (threadIdx.x == 0) out[0] = (float)acc;
    }
}

extern "C" void kernel_launch(void* const* d_in, const int* in_sizes, int n_in,
                              void* d_out, int out_size) {
    const float* model_output = (const float*)d_in[0];
    const void*  target       = (const void*)d_in[1];
    float* out = (float*)d_out;

    row_sum_kernel<<<NTOK, 256>>>(model_output);
    finalize_kernel<<<1, 256>>>(model_output, target, out);
}

// round 3
// speedup vs baseline: 1.1565x; 1.1565x over previous
#include <cuda_runtime.h>
#include <math.h>

#define VOCAB 32000
#define NTOK  4096

// Scratch: per-row loss contributions (allocation-free per harness rules)
__device__ float g_row_loss[NTOK];

// ---------------------------------------------------------------------------
// Kernel 1: one block per row. Streams the row (float4), reduces the sum,
// then thread 0 computes the full smoothed-KL row loss in double:
//   row_loss(t != 0) = K1 - base*(S - x[row][0] - x[row][t]) - conf*x[row][t]
//   row_loss(t == 0) = 0
// Target dtype (int32 vs int64) resolved by a cheap warp-ballot probe over
// the first 32 odd int32 words (all-zero <=> int64 high words).
// ---------------------------------------------------------------------------
__global__ void __launch_bounds__(256) row_loss_kernel(
    const float* __restrict__ x,
    const void*  __restrict__ target_raw)
{
    const int row = blockIdx.x;
    const size_t rowoff = (size_t)row * VOCAB;
    const float4* __restrict__ p = reinterpret_cast<const float4*>(x + rowoff);
    const int nvec = VOCAB / 4;  // 8000

    __shared__ bool s_is64;
    if (threadIdx.x < 32) {
        // probe: odd int32 words of the first 32 "slots"
        const int* t32 = (const int*)target_raw;
        int v = t32[2 * threadIdx.x + 1];
        unsigned any_nonzero = __ballot_sync(0xFFFFFFFFu, v != 0);
        if (threadIdx.x == 0) s_is64 = (any_nonzero == 0);
    }

    float s = 0.0f;
    #pragma unroll 4
    for (int i = threadIdx.x; i < nvec; i += 256) {
        float4 v = p[i];
        s += (v.x + v.y) + (v.z + v.w);
    }

    // warp reduce
    #pragma unroll
    for (int o = 16; o > 0; o >>= 1)
        s += __shfl_xor_sync(0xFFFFFFFFu, s, o);

    __shared__ float wsum[8];
    const int warp = threadIdx.x >> 5;
    if ((threadIdx.x & 31) == 0) wsum[warp] = s;
    __syncthreads();

    if (threadIdx.x == 0) {
        float S = 0.0f;
        #pragma unroll
        for (int w = 0; w < 8; w++) S += wsum[w];

        const long long t = s_is64 ? ((const long long*)target_raw)[row]
                                   : (long long)((const int*)target_raw)[row];

        float loss = 0.0f;
        if (t > 0 && t < VOCAB) {
            const double base = 0.1 / 31999.0;   // SMOOTHING / (V-1)
            const double conf = 0.9;             // 1 - SMOOTHING
            const double K1 = (double)(VOCAB - 2) * base * log(base)
                            + conf * log(conf);
            const double x0 = (double)x[rowoff];          // L1/L2 hit
            const double xt = (double)x[rowoff + (size_t)t];
            loss = (float)(K1 - base * ((double)S - x0 - xt) - conf * xt);
        }
        g_row_loss[row] = loss;
    }
}

// ---------------------------------------------------------------------------
// Kernel 2: reduce 4096 contiguous floats in double, write scalar fp32.
// ---------------------------------------------------------------------------
__global__ void __launch_bounds__(256) reduce_kernel(float* __restrict__ out) {
    double acc = 0.0;
    const float4* p = reinterpret_cast<const float4*>(g_row_loss);
    for (int i = threadIdx.x; i < NTOK / 4; i += 256) {
        float4 v = p[i];
        acc += ((double)v.x + (double)v.y) + ((double)v.z + (double)v.w);
    }

    #pragma unroll
    for (int o = 16; o > 0; o >>= 1)
        acc += __shfl_xor_sync(0xFFFFFFFFu, acc, o);

    __shared__ double wsum[8];
    const int warp = threadIdx.x >> 5;
    if ((threadIdx.x & 31) == 0) wsum[warp] = acc;
    __syncthreads();

    if (threadIdx.x == 0) {
        double tot = 0.0;
        #pragma unroll
        for (int w = 0; w < 8; w++) tot += wsum[w];
        out[0] = (float)tot;
    }
}

extern "C" void kernel_launch(void* const* d_in, const int* in_sizes, int n_in,
                              void* d_out, int out_size) {
    const float* model_output = (const float*)d_in[0];
    const void*  target       = (const void*)d_in[1];
    float* out = (float*)d_out;

    row_loss_kernel<<<NTOK, 256>>>(model_output, target);
    reduce_kernel<<<1, 256>>>(out);
}